// round 12
// baseline (speedup 1.0000x reference)
#include <cuda_runtime.h>
#include <cuda_fp16.h>
#include <cstdint>

#define BT_N 32768
#define D_N  256
#define K_N  8192

#define OUT_Q    0
#define OUT_IDX  (BT_N * D_N)
#define OUT_LOSS (BT_N * D_N + BT_N)

#define SXF 20.0f
#define SEF 1040384.0f           // 8192 * 127
#define TMIN_C (-2.0f / (SXF * SEF))

// ---------------- scratch ---------------------------------------------------
__device__ float  g_s1[BT_N];
__device__ int    g_idx[BT_N];
__device__ double g_sumsq;
// int8 operands, pre-swizzled SW128 (rows of 128B = k-chunk of 128 elems):
__device__ signed char g_Ap8[256][2][16384];   // [m-tile][chunk][128x128B]
__device__ signed char g_Bp8[32][2][32768];    // [n-tile][chunk][256x128B]
// Per-row, per-8-col-group: fp16 of (-2*maxdot)  (d~ = s1 + this)
__device__ __half g_tmin[BT_N][1024];

__global__ void init_kernel() { g_sumsq = 0.0; }

// ---------------- helpers ---------------------------------------------------
__device__ __forceinline__ uint32_t smem_u32(const void* p) {
    uint32_t a;
    asm("{ .reg .u64 t; cvta.to.shared.u64 t, %1; cvt.u32.u64 %0, t; }"
        : "=r"(a) : "l"(p));
    return a;
}
#define SWZ128(o) ((o) ^ (((o) >> 3) & 0x70))

#define CP_A16(s, g) asm volatile("cp.async.cg.shared.global [%0], [%1], 16;\n" :: "r"(s), "l"(g))
#define CP_COMMIT()  asm volatile("cp.async.commit_group;\n" ::: "memory")

template <int N> __device__ __forceinline__ void cp_wait() {
    asm volatile("cp.async.wait_group %0;\n" :: "n"(N) : "memory");
}

__device__ __forceinline__ void ldsm4(uint32_t& r0, uint32_t& r1, uint32_t& r2,
                                      uint32_t& r3, uint32_t addr) {
    asm volatile("ldmatrix.sync.aligned.m8n8.x4.shared.b16 {%0,%1,%2,%3}, [%4];"
                 : "=r"(r0), "=r"(r1), "=r"(r2), "=r"(r3) : "r"(addr));
}

// ---------------------------------------------------------------------------
// Row squared-norm — IDENTICAL to round-1 (bit-exact s1 required).
// ---------------------------------------------------------------------------
__global__ void rownorm_kernel(const float* __restrict__ x) {
    int row = blockIdx.x * blockDim.x + threadIdx.x;
    if (row >= BT_N) return;
    const float4* p = reinterpret_cast<const float4*>(x + (size_t)row * D_N);
    float a0 = 0.f, a1 = 0.f, a2 = 0.f, a3 = 0.f;
#pragma unroll 8
    for (int c = 0; c < D_N / 4; ++c) {
        float4 v = __ldg(p + c);
        a0 = __fadd_rn(a0, __fmul_rn(v.x, v.x));
        a1 = __fadd_rn(a1, __fmul_rn(v.y, v.y));
        a2 = __fadd_rn(a2, __fmul_rn(v.z, v.z));
        a3 = __fadd_rn(a3, __fmul_rn(v.w, v.w));
    }
    g_s1[row] = __fadd_rn(__fadd_rn(a0, a2), __fadd_rn(a1, a3));
}

// ---------------------------------------------------------------------------
// int8 pack: thread = 16 consecutive elements (one 16B swizzle unit).
// ---------------------------------------------------------------------------
union S8x16 { signed char b[16]; uint4 u; };

__device__ __forceinline__ void cvt16_s8(const float* src, float scale, S8x16& out) {
#pragma unroll
    for (int q = 0; q < 4; ++q) {
        float4 t = __ldg((const float4*)src + q);
        float vv[4] = {t.x, t.y, t.z, t.w};
#pragma unroll
        for (int i = 0; i < 4; ++i) {
            int v = __float2int_rn(vv[i] * scale);
            v = v > 127 ? 127 : (v < -128 ? -128 : v);
            out.b[q * 4 + i] = (signed char)v;
        }
    }
}

__global__ void pack_x_kernel(const float* __restrict__ x) {
    int n = blockIdx.x * blockDim.x + threadIdx.x;     // BT_N * 16
    if (n >= BT_N * 16) return;
    int row = n >> 4, g = n & 15;
    int chunk = g >> 3, ci = (g & 7) * 16;
    S8x16 v;
    cvt16_s8(x + (size_t)row * 256 + g * 16, SXF, v);
    int rr = row & 127, mt = row >> 7;
    uint32_t off = SWZ128((uint32_t)(rr * 128 + ci));
    *(uint4*)(g_Ap8[mt][chunk] + off) = v.u;
}

__global__ void pack_e_kernel(const float* __restrict__ cb) {
    int n = blockIdx.x * blockDim.x + threadIdx.x;     // K_N * 16
    if (n >= K_N * 16) return;
    int row = n >> 4, g = n & 15;
    int chunk = g >> 3, ci = (g & 7) * 16;
    S8x16 v;
    cvt16_s8(cb + (size_t)row * 256 + g * 16, SEF, v);
    int rr = row & 255, nt = row >> 8;
    uint32_t off = SWZ128((uint32_t)(rr * 128 + ci));
    *(uint4*)(g_Bp8[nt][chunk] + off) = v.u;
}

// ---------------------------------------------------------------------------
// Selection GEMM: int8 mma.sync m16n8k32 s32 acc, K=256 (2 chunks of 128).
// CTA 128x256, 256 threads, 8 warps (2x4), warp tile 64x64 — R6 structure.
// All operands 96KB SMEM; 8 load stages (12KB each = one 32B k-slice of A+B),
// all issued upfront, per-stage wait_group lookahead; single epilogue.
// ---------------------------------------------------------------------------
#define GEMM_SMEM 98304   // A: 2 x 16KB @0, B: 2 x 32KB @32768

__global__ __launch_bounds__(256, 1) void select_gemm_imma() {
    extern __shared__ char smem[];
    const uint32_t sbA = smem_u32(smem);
    const uint32_t sbB = sbA + 32768u;
    const int tid  = threadIdx.x;
    const int lane = tid & 31;
    const int wid  = tid >> 5;
    const int wr   = wid >> 2;       // 0..1
    const int wc   = wid & 3;        // 0..3
    const int mt   = blockIdx.y;
    const int ntile = blockIdx.x;

    // issue all 8 stage loads upfront (stage = chunk c, k-slice s of 32B)
    {
        const int rA = tid >> 1, hA = tid & 1;
#pragma unroll
        for (int t = 0; t < 8; ++t) {
            const int c = t >> 2, s = t & 3;
            {
                uint32_t off = SWZ128((uint32_t)(rA * 128 + s * 32 + hA * 16));
                CP_A16(sbA + (uint32_t)c * 16384u + off, g_Ap8[mt][c] + off);
            }
#pragma unroll
            for (int u = 0; u < 2; ++u) {
                int r = (tid + u * 256) >> 1, h = tid & 1;
                uint32_t off = SWZ128((uint32_t)(r * 128 + s * 32 + h * 16));
                CP_A16(sbB + (uint32_t)c * 32768u + off, g_Bp8[ntile][c] + off);
            }
            CP_COMMIT();
        }
    }

    int acc[4][8][4];
#pragma unroll
    for (int mi = 0; mi < 4; ++mi)
#pragma unroll
        for (int ni = 0; ni < 8; ++ni)
#pragma unroll
            for (int q = 0; q < 4; ++q) acc[mi][ni][q] = 0;

    const int arow_lo = wr * 64 + (lane & 15);
    const uint32_t a_csel = (uint32_t)((lane >> 4) << 4);
    const int brow_lo = wc * 64 + ((lane >> 4) << 3) + (lane & 7);
    const uint32_t b_csel = (uint32_t)(((lane >> 3) & 1) << 4);

    auto compute_step = [&](uint32_t sA, uint32_t sB, int s) {
        uint32_t a[4][4];
#pragma unroll
        for (int mi = 0; mi < 4; ++mi) {
            int arow = arow_lo + mi * 16;
            uint32_t addr = sA + (uint32_t)arow * 128u +
                            (((uint32_t)(s * 32) + a_csel) ^ (uint32_t)((arow & 7) << 4));
            ldsm4(a[mi][0], a[mi][1], a[mi][2], a[mi][3], addr);
        }
        uint32_t b[8][2];
#pragma unroll
        for (int p = 0; p < 4; ++p) {
            int brow = brow_lo + p * 16;
            uint32_t kb = b_csel + (uint32_t)(s * 32);
            uint32_t addr = sB + (uint32_t)brow * 128u +
                            (kb ^ (uint32_t)((brow & 7) << 4));
            ldsm4(b[2 * p][0], b[2 * p][1], b[2 * p + 1][0], b[2 * p + 1][1], addr);
        }
#pragma unroll
        for (int mi = 0; mi < 4; ++mi)
#pragma unroll
            for (int ni = 0; ni < 8; ++ni) {
                asm volatile(
                    "mma.sync.aligned.m16n8k32.row.col.s32.s8.s8.s32 "
                    "{%0,%1,%2,%3}, {%4,%5,%6,%7}, {%8,%9}, {%0,%1,%2,%3};"
                    : "+r"(acc[mi][ni][0]), "+r"(acc[mi][ni][1]),
                      "+r"(acc[mi][ni][2]), "+r"(acc[mi][ni][3])
                    : "r"(a[mi][0]), "r"(a[mi][1]), "r"(a[mi][2]), "r"(a[mi][3]),
                      "r"(b[ni][0]), "r"(b[ni][1]));
            }
    };

#define GSTEP(t)                                                         \
    cp_wait<7 - (t)>();                                                  \
    __syncthreads();                                                     \
    compute_step(sbA + (uint32_t)((t) >> 2) * 16384u,                    \
                 sbB + (uint32_t)((t) >> 2) * 32768u, (t) & 3);

    GSTEP(0) GSTEP(1) GSTEP(2) GSTEP(3)
    GSTEP(4) GSTEP(5) GSTEP(6) GSTEP(7)
#undef GSTEP

    // epilogue: per 8-col group (one ni octet) max of int dot -> tmin
    const int g   = lane >> 2;
    const int tig = lane & 3;
#pragma unroll
    for (int mi = 0; mi < 4; ++mi) {
        int r_lo = mt * 128 + wr * 64 + mi * 16 + g;
#pragma unroll
        for (int ni = 0; ni < 8; ++ni) {
            int m0 = max(acc[mi][ni][0], acc[mi][ni][1]);
            int m1 = max(acc[mi][ni][2], acc[mi][ni][3]);
            m0 = max(m0, __shfl_xor_sync(0xffffffffu, m0, 1));
            m0 = max(m0, __shfl_xor_sync(0xffffffffu, m0, 2));
            m1 = max(m1, __shfl_xor_sync(0xffffffffu, m1, 1));
            m1 = max(m1, __shfl_xor_sync(0xffffffffu, m1, 2));
            if (tig == 0) {
                int grp = ntile * 32 + wc * 8 + ni;
                g_tmin[r_lo][grp]     = __float2half_rn((float)m0 * TMIN_C);
                g_tmin[r_lo + 8][grp] = __float2half_rn((float)m1 * TMIN_C);
            }
        }
    }
}

// ---------------------------------------------------------------------------
// Exact refine: candidates at 8-column granularity, cooperatively staged into
// SMEM; 8 lanes run the identical fp32 sequential-fmaf chain (bit-exact).
// Margin 3.2e-4 (~9 sigma of int8 selection error).
// ---------------------------------------------------------------------------
#define REFINE_SMEM (8192 + 8 * 8320)

__global__ __launch_bounds__(256) void refine_kernel(
    const float* __restrict__ x, const float* __restrict__ cb,
    float* __restrict__ out_idxf, int write_idxf) {
    extern __shared__ char rsm[];
    const int tid = threadIdx.x, lane = tid & 31, wid = tid >> 5;
    const int row = blockIdx.x * 8 + wid;
    float* xs = (float*)rsm + wid * 256;
    float* es = (float*)(rsm + 8192 + wid * 8320);

#pragma unroll
    for (int i = 0; i < 8; ++i)
        xs[lane + 32 * i] = x[(size_t)row * 256 + lane + 32 * i];
    const float s1r = g_s1[row];
    __syncwarp();

    float tm[32];
    float gmin = __int_as_float(0x7f800000);
#pragma unroll
    for (int i = 0; i < 32; ++i) {
        tm[i] = s1r + __half2float(g_tmin[row][lane + 32 * i]);
        gmin = fminf(gmin, tm[i]);
    }
#pragma unroll
    for (int o = 16; o > 0; o >>= 1)
        gmin = fminf(gmin, __shfl_xor_sync(0xffffffffu, gmin, o));

    const float thr = gmin + 3.2e-4f;
    unsigned long long best = ~0ULL;

#pragma unroll 1
    for (int i = 0; i < 32; ++i) {
        unsigned msk = __ballot_sync(0xffffffffu, tm[i] <= thr);
        while (msk) {
            int l = __ffs(msk) - 1;
            msk &= msk - 1;
            int grp = l + 32 * i;
            int jbase = grp * 8;
            const float4* src = (const float4*)(cb + (size_t)jbase * 256);
#pragma unroll
            for (int it = 0; it < 16; ++it) {
                int idx = it * 32 + lane;
                int r = idx >> 6, c4 = idx & 63;
                float4 v = __ldg(src + r * 64 + c4);
                *(float4*)&es[r * 260 + c4 * 4] = v;
            }
            __syncwarp();
            if (lane < 8) {
                const float* e = es + lane * 260;
                float acc = 0.f;
#pragma unroll 8
                for (int k = 0; k < 256; ++k)
                    acc = __fmaf_rn(xs[k], e[k], acc);
                float d = __fsub_rn(s1r, __fmul_rn(2.0f, acc));
                int j = jbase + lane;
                unsigned long long p =
                    ((unsigned long long)__float_as_uint(d) << 32) | (unsigned)j;
                best = min(best, p);
            }
            __syncwarp();
        }
    }
#pragma unroll
    for (int o = 16; o > 0; o >>= 1) {
        unsigned long long q = __shfl_xor_sync(0xffffffffu, best, o);
        best = min(best, q);
    }
    if (lane == 0) {
        int bj = (int)(best & 0xffffffffULL);
        g_idx[row] = bj;
        if (write_idxf) out_idxf[row] = (float)bj;
    }
}

// ---------------------------------------------------------------------------
// Gather: warp per row, float4-coalesced; fp64 MSE accumulation.
// ---------------------------------------------------------------------------
__global__ __launch_bounds__(256) void gather_mse_kernel(
    const float* __restrict__ x, const float* __restrict__ cb,
    float* __restrict__ outq) {
    __shared__ double red[256];
    const int lane = threadIdx.x & 31, wid = threadIdx.x >> 5;
    const int row = blockIdx.x * 8 + wid;
    const int idx = g_idx[row];
    const float4* e = (const float4*)(cb + (size_t)idx * 256);
    const float4* xr = (const float4*)(x + (size_t)row * 256);
    float4* o = (float4*)(outq + (size_t)row * 256);
    double s = 0.0;
#pragma unroll
    for (int i = 0; i < 2; ++i) {
        int c = lane + i * 32;
        float4 q = __ldg(e + c);
        float4 v = __ldg(xr + c);
        o[c] = q;
        float d0 = __fsub_rn(q.x, v.x), d1 = __fsub_rn(q.y, v.y);
        float d2 = __fsub_rn(q.z, v.z), d3 = __fsub_rn(q.w, v.w);
        s += (double)d0 * d0 + (double)d1 * d1 + (double)d2 * d2 + (double)d3 * d3;
    }
    red[threadIdx.x] = s;
    __syncthreads();
    for (int o2 = 128; o2 > 0; o2 >>= 1) {
        if (threadIdx.x < o2) red[threadIdx.x] += red[threadIdx.x + o2];
        __syncthreads();
    }
    if (threadIdx.x == 0) atomicAdd(&g_sumsq, red[0]);
}

__global__ void finalize_kernel(float* __restrict__ out_loss) {
    double m = g_sumsq / (double)(BT_N * D_N);
    float mf = (float)m;
    out_loss[0] = __fadd_rn(mf, __fmul_rn(0.25f, mf));
}

extern "C" void kernel_launch(void* const* d_in, const int* in_sizes, int n_in,
                              void* d_out, int out_size) {
    const float* x  = (const float*)d_in[0];
    const float* cb = (const float*)d_in[1];
    float* out = (float*)d_out;
    const int full = (out_size >= OUT_LOSS + 1);

    cudaFuncSetAttribute(select_gemm_imma,
                         cudaFuncAttributeMaxDynamicSharedMemorySize, GEMM_SMEM);
    cudaFuncSetAttribute(refine_kernel,
                         cudaFuncAttributeMaxDynamicSharedMemorySize, REFINE_SMEM);

    init_kernel<<<1, 1>>>();
    rownorm_kernel<<<BT_N / 256, 256>>>(x);
    pack_x_kernel<<<(BT_N * 16) / 256, 256>>>(x);
    pack_e_kernel<<<(K_N * 16) / 256, 256>>>(cb);

    dim3 ggrid(K_N / 256, BT_N / 128);
    select_gemm_imma<<<ggrid, 256, GEMM_SMEM>>>();

    refine_kernel<<<BT_N / 8, 256, REFINE_SMEM>>>(x, cb,
                                                  full ? (out + OUT_IDX) : (float*)0,
                                                  full ? 1 : 0);
    if (out_size >= BT_N * D_N) {
        gather_mse_kernel<<<BT_N / 8, 256>>>(x, cb, out + OUT_Q);
    }
    if (full) {
        finalize_kernel<<<1, 1>>>(out + OUT_LOSS);
    }
}

// round 13
// speedup vs baseline: 1.0541x; 1.0541x over previous
#include <cuda_runtime.h>
#include <cuda_fp16.h>
#include <cstdint>

#define BT_N 32768
#define D_N  256
#define K_N  8192

#define OUT_Q    0
#define OUT_IDX  (BT_N * D_N)
#define OUT_LOSS (BT_N * D_N + BT_N)

#define SXF 20.0f
#define SEF 1040384.0f           // 8192 * 127
#define TMIN_C (-2.0f / (SXF * SEF))

// ---------------- scratch ---------------------------------------------------
__device__ float  g_s1[BT_N];
__device__ double g_sumsq;
// int8 operands, pre-swizzled SW128 (rows of 128B = k-chunk of 128 elems):
__device__ signed char g_Ap8[256][2][16384];   // [m-tile][chunk][128x128B]
__device__ signed char g_Bp8[32][2][32768];    // [n-tile][chunk][256x128B]
// Per-row, per-8-col-group: fp16 of (-2*maxdot)  (d~ = s1 + this)
__device__ __half g_tmin[BT_N][1024];

__global__ void init_kernel() { g_sumsq = 0.0; }

// ---------------- helpers ---------------------------------------------------
__device__ __forceinline__ uint32_t smem_u32(const void* p) {
    uint32_t a;
    asm("{ .reg .u64 t; cvta.to.shared.u64 t, %1; cvt.u32.u64 %0, t; }"
        : "=r"(a) : "l"(p));
    return a;
}
#define SWZ128(o) ((o) ^ (((o) >> 3) & 0x70))

#define CP_A16(s, g) asm volatile("cp.async.cg.shared.global [%0], [%1], 16;\n" :: "r"(s), "l"(g))
#define CP_COMMIT()  asm volatile("cp.async.commit_group;\n" ::: "memory")
#define CP_WAIT(n)   asm volatile("cp.async.wait_group %0;\n" :: "n"(n) : "memory")

__device__ __forceinline__ void ldsm4(uint32_t& r0, uint32_t& r1, uint32_t& r2,
                                      uint32_t& r3, uint32_t addr) {
    asm volatile("ldmatrix.sync.aligned.m8n8.x4.shared.b16 {%0,%1,%2,%3}, [%4];"
                 : "=r"(r0), "=r"(r1), "=r"(r2), "=r"(r3) : "r"(addr));
}

// ---------------------------------------------------------------------------
// Row squared-norm — IDENTICAL to round-1 (bit-exact s1 required).
// ---------------------------------------------------------------------------
__global__ void rownorm_kernel(const float* __restrict__ x) {
    int row = blockIdx.x * blockDim.x + threadIdx.x;
    if (row >= BT_N) return;
    const float4* p = reinterpret_cast<const float4*>(x + (size_t)row * D_N);
    float a0 = 0.f, a1 = 0.f, a2 = 0.f, a3 = 0.f;
#pragma unroll 8
    for (int c = 0; c < D_N / 4; ++c) {
        float4 v = __ldg(p + c);
        a0 = __fadd_rn(a0, __fmul_rn(v.x, v.x));
        a1 = __fadd_rn(a1, __fmul_rn(v.y, v.y));
        a2 = __fadd_rn(a2, __fmul_rn(v.z, v.z));
        a3 = __fadd_rn(a3, __fmul_rn(v.w, v.w));
    }
    g_s1[row] = __fadd_rn(__fadd_rn(a0, a2), __fadd_rn(a1, a3));
}

// ---------------------------------------------------------------------------
// int8 pack: thread = 16 consecutive elements (one 16B swizzle unit).
// ---------------------------------------------------------------------------
union S8x16 { signed char b[16]; uint4 u; };

__device__ __forceinline__ void cvt16_s8(const float* src, float scale, S8x16& out) {
#pragma unroll
    for (int q = 0; q < 4; ++q) {
        float4 t = __ldg((const float4*)src + q);
        float vv[4] = {t.x, t.y, t.z, t.w};
#pragma unroll
        for (int i = 0; i < 4; ++i) {
            int v = __float2int_rn(vv[i] * scale);
            v = v > 127 ? 127 : (v < -128 ? -128 : v);
            out.b[q * 4 + i] = (signed char)v;
        }
    }
}

__global__ void pack_x_kernel(const float* __restrict__ x) {
    int n = blockIdx.x * blockDim.x + threadIdx.x;     // BT_N * 16
    if (n >= BT_N * 16) return;
    int row = n >> 4, g = n & 15;
    int chunk = g >> 3, ci = (g & 7) * 16;
    S8x16 v;
    cvt16_s8(x + (size_t)row * 256 + g * 16, SXF, v);
    int rr = row & 127, mt = row >> 7;
    uint32_t off = SWZ128((uint32_t)(rr * 128 + ci));
    *(uint4*)(g_Ap8[mt][chunk] + off) = v.u;
}

__global__ void pack_e_kernel(const float* __restrict__ cb) {
    int n = blockIdx.x * blockDim.x + threadIdx.x;     // K_N * 16
    if (n >= K_N * 16) return;
    int row = n >> 4, g = n & 15;
    int chunk = g >> 3, ci = (g & 7) * 16;
    S8x16 v;
    cvt16_s8(cb + (size_t)row * 256 + g * 16, SEF, v);
    int rr = row & 255, nt = row >> 8;
    uint32_t off = SWZ128((uint32_t)(rr * 128 + ci));
    *(uint4*)(g_Bp8[nt][chunk] + off) = v.u;
}

// ---------------------------------------------------------------------------
// Selection GEMM: int8 mma.sync m16n8k32 s32 acc, K=256 (2 chunks of 128).
// R6 structure: CTA 128x256, 256 threads, 8 warps (2x4), warp tile 64x64,
// double-buffered LINEAR chunk loads (A 16KB + B 32KB per chunk, tid*16).
// Epilogue: per 8-col group: g_tmin[row][grp] = half(-2*maxdot scaled).
// ---------------------------------------------------------------------------
#define GEMM_SMEM 98304   // A: 2 x 16KB @0, B: 2 x 32KB @32768

__global__ __launch_bounds__(256, 1) void select_gemm_imma() {
    extern __shared__ char smem[];
    const uint32_t sb = smem_u32(smem);
    const int tid  = threadIdx.x;
    const int lane = tid & 31;
    const int wid  = tid >> 5;
    const int wr   = wid >> 2;       // 0..1
    const int wc   = wid & 3;        // 0..3
    const int mt   = blockIdx.y;
    const int ntile = blockIdx.x;

    // linear, fully-coalesced chunk loads (same structure as R6)
    auto load_chunk = [&](int c) {
        uint32_t sA = sb + (uint32_t)c * 16384u;
        uint32_t sB = sb + 32768u + (uint32_t)c * 32768u;
        const uint4* ga = (const uint4*)g_Ap8[mt][c] + tid;       // 1024 uint4
        const uint4* gb = (const uint4*)g_Bp8[ntile][c] + tid;    // 2048 uint4
#pragma unroll
        for (int i = 0; i < 4; ++i)
            CP_A16(sA + (uint32_t)(tid + i * 256) * 16u, ga + i * 256);
#pragma unroll
        for (int i = 0; i < 8; ++i)
            CP_A16(sB + (uint32_t)(tid + i * 256) * 16u, gb + i * 256);
        CP_COMMIT();
    };

    load_chunk(0);
    load_chunk(1);

    int acc[4][8][4];
#pragma unroll
    for (int mi = 0; mi < 4; ++mi)
#pragma unroll
        for (int ni = 0; ni < 8; ++ni)
#pragma unroll
            for (int q = 0; q < 4; ++q) acc[mi][ni][q] = 0;

    const int arow_lo = wr * 64 + (lane & 15);
    const uint32_t a_csel = (uint32_t)((lane >> 4) << 4);
    const int brow_lo = wc * 64 + ((lane >> 4) << 3) + (lane & 7);
    const uint32_t b_csel = (uint32_t)(((lane >> 3) & 1) << 4);

#pragma unroll 1
    for (int c = 0; c < 2; ++c) {
        if (c == 0) { CP_WAIT(1); } else { CP_WAIT(0); }
        __syncthreads();

        const uint32_t sA = sb + (uint32_t)c * 16384u;
        const uint32_t sB = sb + 32768u + (uint32_t)c * 32768u;

#pragma unroll
        for (int s = 0; s < 4; ++s) {          // 32-elem k-slices within chunk
            uint32_t a[4][4];
#pragma unroll
            for (int mi = 0; mi < 4; ++mi) {
                int arow = arow_lo + mi * 16;
                uint32_t addr = sA + (uint32_t)arow * 128u +
                                (((uint32_t)(s * 32) + a_csel) ^ (uint32_t)((arow & 7) << 4));
                ldsm4(a[mi][0], a[mi][1], a[mi][2], a[mi][3], addr);
            }
            uint32_t b[8][2];
#pragma unroll
            for (int p = 0; p < 4; ++p) {
                int brow = brow_lo + p * 16;
                uint32_t kb = b_csel + (uint32_t)(s * 32);
                uint32_t addr = sB + (uint32_t)brow * 128u +
                                (kb ^ (uint32_t)((brow & 7) << 4));
                ldsm4(b[2 * p][0], b[2 * p][1], b[2 * p + 1][0], b[2 * p + 1][1], addr);
            }
#pragma unroll
            for (int mi = 0; mi < 4; ++mi)
#pragma unroll
                for (int ni = 0; ni < 8; ++ni) {
                    asm volatile(
                        "mma.sync.aligned.m16n8k32.row.col.s32.s8.s8.s32 "
                        "{%0,%1,%2,%3}, {%4,%5,%6,%7}, {%8,%9}, {%0,%1,%2,%3};"
                        : "+r"(acc[mi][ni][0]), "+r"(acc[mi][ni][1]),
                          "+r"(acc[mi][ni][2]), "+r"(acc[mi][ni][3])
                        : "r"(a[mi][0]), "r"(a[mi][1]), "r"(a[mi][2]), "r"(a[mi][3]),
                          "r"(b[ni][0]), "r"(b[ni][1]));
                }
        }
        __syncthreads();
    }

    // epilogue: per 8-col group (one ni octet) max of int dot -> tmin
    const int g   = lane >> 2;
    const int tig = lane & 3;
#pragma unroll
    for (int mi = 0; mi < 4; ++mi) {
        int r_lo = mt * 128 + wr * 64 + mi * 16 + g;
#pragma unroll
        for (int ni = 0; ni < 8; ++ni) {
            int m0 = max(acc[mi][ni][0], acc[mi][ni][1]);
            int m1 = max(acc[mi][ni][2], acc[mi][ni][3]);
            m0 = max(m0, __shfl_xor_sync(0xffffffffu, m0, 1));
            m0 = max(m0, __shfl_xor_sync(0xffffffffu, m0, 2));
            m1 = max(m1, __shfl_xor_sync(0xffffffffu, m1, 1));
            m1 = max(m1, __shfl_xor_sync(0xffffffffu, m1, 2));
            if (tig == 0) {
                int grp = ntile * 32 + wc * 8 + ni;
                g_tmin[r_lo][grp]     = __float2half_rn((float)m0 * TMIN_C);
                g_tmin[r_lo + 8][grp] = __float2half_rn((float)m1 * TMIN_C);
            }
        }
    }
}

// ---------------------------------------------------------------------------
// Exact refine + fused gather/loss. Candidates at 8-column granularity,
// cooperatively staged; 8 lanes run the identical fp32 sequential-fmaf chain
// (bit-exact argmin). Winner's codebook row is then gathered coalesced by the
// same warp: writes quantized output, idx, and accumulates fp64 MSE.
// ---------------------------------------------------------------------------
#define REFINE_SMEM (8192 + 8 * 8320 + 64)

__global__ __launch_bounds__(256) void refine_gather_kernel(
    const float* __restrict__ x, const float* __restrict__ cb,
    float* __restrict__ outq, float* __restrict__ out_idxf,
    int write_out) {
    extern __shared__ char rsm[];
    const int tid = threadIdx.x, lane = tid & 31, wid = tid >> 5;
    const int row = blockIdx.x * 8 + wid;
    float* xs = (float*)rsm + wid * 256;
    float* es = (float*)(rsm + 8192 + wid * 8320);
    double* wsum = (double*)(rsm + 8192 + 8 * 8320);

#pragma unroll
    for (int i = 0; i < 8; ++i)
        xs[lane + 32 * i] = x[(size_t)row * 256 + lane + 32 * i];
    const float s1r = g_s1[row];
    __syncwarp();

    float tm[32];
    float gmin = __int_as_float(0x7f800000);
#pragma unroll
    for (int i = 0; i < 32; ++i) {
        tm[i] = s1r + __half2float(g_tmin[row][lane + 32 * i]);
        gmin = fminf(gmin, tm[i]);
    }
#pragma unroll
    for (int o = 16; o > 0; o >>= 1)
        gmin = fminf(gmin, __shfl_xor_sync(0xffffffffu, gmin, o));

    const float thr = gmin + 3.2e-4f;
    unsigned long long best = ~0ULL;

#pragma unroll 1
    for (int i = 0; i < 32; ++i) {
        unsigned msk = __ballot_sync(0xffffffffu, tm[i] <= thr);
        while (msk) {
            int l = __ffs(msk) - 1;
            msk &= msk - 1;
            int grp = l + 32 * i;
            int jbase = grp * 8;
            const float4* src = (const float4*)(cb + (size_t)jbase * 256);
#pragma unroll
            for (int it = 0; it < 16; ++it) {
                int idx = it * 32 + lane;
                int r = idx >> 6, c4 = idx & 63;
                float4 v = __ldg(src + r * 64 + c4);
                *(float4*)&es[r * 260 + c4 * 4] = v;
            }
            __syncwarp();
            if (lane < 8) {
                const float* e = es + lane * 260;
                float acc = 0.f;
#pragma unroll 8
                for (int k = 0; k < 256; ++k)
                    acc = __fmaf_rn(xs[k], e[k], acc);
                float d = __fsub_rn(s1r, __fmul_rn(2.0f, acc));
                int j = jbase + lane;
                unsigned long long p =
                    ((unsigned long long)__float_as_uint(d) << 32) | (unsigned)j;
                best = min(best, p);
            }
            __syncwarp();
        }
    }
#pragma unroll
    for (int o = 16; o > 0; o >>= 1) {
        unsigned long long q = __shfl_xor_sync(0xffffffffu, best, o);
        best = min(best, q);
    }
    const int bj = (int)(best & 0xffffffffULL);   // all lanes agree

    // fused gather + fp64 MSE
    double s = 0.0;
    {
        const float4* e = (const float4*)(cb + (size_t)bj * 256);
#pragma unroll
        for (int i = 0; i < 2; ++i) {
            int c = lane + i * 32;
            float4 q = __ldg(e + c);
            float vx = xs[c * 4], vy = xs[c * 4 + 1],
                  vz = xs[c * 4 + 2], vw = xs[c * 4 + 3];
            if (write_out) *((float4*)(outq + (size_t)row * 256) + c) = q;
            float d0 = __fsub_rn(q.x, vx), d1 = __fsub_rn(q.y, vy);
            float d2 = __fsub_rn(q.z, vz), d3 = __fsub_rn(q.w, vw);
            s += (double)d0 * d0 + (double)d1 * d1 + (double)d2 * d2 + (double)d3 * d3;
        }
    }
    // warp-reduce fp64 sum
#pragma unroll
    for (int o = 16; o > 0; o >>= 1)
        s += __shfl_xor_sync(0xffffffffu, s, o);
    if (lane == 0) {
        if (write_out && out_idxf) out_idxf[row] = (float)bj;
        wsum[wid] = s;
    }
    __syncthreads();
    if (tid == 0) {
        double t = 0.0;
#pragma unroll
        for (int w = 0; w < 8; ++w) t += wsum[w];
        atomicAdd(&g_sumsq, t);
    }
}

__global__ void finalize_kernel(float* __restrict__ out_loss) {
    double m = g_sumsq / (double)(BT_N * D_N);
    float mf = (float)m;
    out_loss[0] = __fadd_rn(mf, __fmul_rn(0.25f, mf));
}

extern "C" void kernel_launch(void* const* d_in, const int* in_sizes, int n_in,
                              void* d_out, int out_size) {
    const float* x  = (const float*)d_in[0];
    const float* cb = (const float*)d_in[1];
    float* out = (float*)d_out;
    const int full = (out_size >= OUT_LOSS + 1);
    const int wq   = (out_size >= BT_N * D_N);

    cudaFuncSetAttribute(select_gemm_imma,
                         cudaFuncAttributeMaxDynamicSharedMemorySize, GEMM_SMEM);
    cudaFuncSetAttribute(refine_gather_kernel,
                         cudaFuncAttributeMaxDynamicSharedMemorySize, REFINE_SMEM);

    init_kernel<<<1, 1>>>();
    rownorm_kernel<<<BT_N / 256, 256>>>(x);
    pack_x_kernel<<<(BT_N * 16) / 256, 256>>>(x);
    pack_e_kernel<<<(K_N * 16) / 256, 256>>>(cb);

    dim3 ggrid(K_N / 256, BT_N / 128);
    select_gemm_imma<<<ggrid, 256, GEMM_SMEM>>>();

    refine_gather_kernel<<<BT_N / 8, 256, REFINE_SMEM>>>(
        x, cb,
        wq ? (out + OUT_Q) : (float*)0,
        full ? (out + OUT_IDX) : (float*)0,
        wq ? 1 : 0);
    if (full) {
        finalize_kernel<<<1, 1>>>(out + OUT_LOSS);
    }
}

// round 14
// speedup vs baseline: 1.8717x; 1.7757x over previous
#include <cuda_runtime.h>
#include <cuda_fp16.h>
#include <cstdint>

#define BT_N 32768
#define D_N  256
#define K_N  8192

#define OUT_Q    0
#define OUT_IDX  (BT_N * D_N)
#define OUT_LOSS (BT_N * D_N + BT_N)

// ---------------- scratch ---------------------------------------------------
__device__ float  g_s1[BT_N];
__device__ double g_sumsq;
// Pre-swizzled fp16 operands (SW128 rows of 128B):
__device__ unsigned short g_Ap[256][4][8192];    // [m-tile][k-chunk64][128x64 sw]
__device__ unsigned short g_Bp[32][4][16384];    // [n-tile][k-chunk64][256x64 sw]
// Per-row, per-8-col-group: fp16 of (-2*maxdot)  (d~ = s1 + this)
__device__ __half g_tmin[BT_N][1024];

__global__ void init_kernel() { g_sumsq = 0.0; }

// ---------------- helpers ---------------------------------------------------
__device__ __forceinline__ uint32_t smem_u32(const void* p) {
    uint32_t a;
    asm("{ .reg .u64 t; cvta.to.shared.u64 t, %1; cvt.u32.u64 %0, t; }"
        : "=r"(a) : "l"(p));
    return a;
}
#define SWZ128(o) ((o) ^ (((o) >> 3) & 0x70))

#define CP_A16(s, g) asm volatile("cp.async.cg.shared.global [%0], [%1], 16;\n" :: "r"(s), "l"(g))
#define CP_COMMIT()  asm volatile("cp.async.commit_group;\n" ::: "memory")
#define CP_WAIT(n)   asm volatile("cp.async.wait_group %0;\n" :: "n"(n) : "memory")

__device__ __forceinline__ void ldsm4(uint32_t& r0, uint32_t& r1, uint32_t& r2,
                                      uint32_t& r3, uint32_t addr) {
    asm volatile("ldmatrix.sync.aligned.m8n8.x4.shared.b16 {%0,%1,%2,%3}, [%4];"
                 : "=r"(r0), "=r"(r1), "=r"(r2), "=r"(r3) : "r"(addr));
}

// ---------------------------------------------------------------------------
// Row squared-norm — IDENTICAL to round-1 (bit-exact s1 required).
// ---------------------------------------------------------------------------
__global__ void rownorm_kernel(const float* __restrict__ x) {
    int row = blockIdx.x * blockDim.x + threadIdx.x;
    if (row >= BT_N) return;
    const float4* p = reinterpret_cast<const float4*>(x + (size_t)row * D_N);
    float a0 = 0.f, a1 = 0.f, a2 = 0.f, a3 = 0.f;
#pragma unroll 8
    for (int c = 0; c < D_N / 4; ++c) {
        float4 v = __ldg(p + c);
        a0 = __fadd_rn(a0, __fmul_rn(v.x, v.x));
        a1 = __fadd_rn(a1, __fmul_rn(v.y, v.y));
        a2 = __fadd_rn(a2, __fmul_rn(v.z, v.z));
        a3 = __fadd_rn(a3, __fmul_rn(v.w, v.w));
    }
    g_s1[row] = __fadd_rn(__fadd_rn(a0, a2), __fadd_rn(a1, a3));
}

// ---------------------------------------------------------------------------
// Pack fp16 into swizzled blocked layout; thread = 8 elems (16B unit).
// ---------------------------------------------------------------------------
union U16x8 { unsigned short h[8]; uint4 u; };

__device__ __forceinline__ void cvt8(const float* src, U16x8& out) {
    float4 v0 = __ldg((const float4*)src);
    float4 v1 = __ldg((const float4*)src + 1);
    float vv[8] = {v0.x, v0.y, v0.z, v0.w, v1.x, v1.y, v1.z, v1.w};
#pragma unroll
    for (int i = 0; i < 8; ++i) {
        __half h = __float2half_rn(vv[i]);
        out.h[i] = *reinterpret_cast<unsigned short*>(&h);
    }
}

__global__ void pack_x_kernel(const float* __restrict__ x) {
    int n = blockIdx.x * blockDim.x + threadIdx.x;
    if (n >= BT_N * 32) return;
    int row = n >> 5, g = n & 31;
    int kc = g >> 3, ci = (g & 7) * 8;
    U16x8 v;
    cvt8(x + (size_t)row * 256 + g * 8, v);
    int rr = row & 127, mt = row >> 7;
    uint32_t off = SWZ128(rr * 128 + ci * 2);
    *(uint4*)((char*)g_Ap[mt][kc] + off) = v.u;
}

__global__ void pack_e_kernel(const float* __restrict__ cb) {
    int n = blockIdx.x * blockDim.x + threadIdx.x;
    if (n >= K_N * 32) return;
    int row = n >> 5, g = n & 31;
    int kc = g >> 3, ci = (g & 7) * 8;
    U16x8 v;
    cvt8(cb + (size_t)row * 256 + g * 8, v);
    int rr = row & 255, nt = row >> 8;
    uint32_t off = SWZ128(rr * 128 + ci * 2);
    *(uint4*)((char*)g_Bp[nt][kc] + off) = v.u;
}

// ---------------------------------------------------------------------------
// Selection GEMM (R6 structure, the empirical winner): fp16 mma.sync / fp16
// acc, K=256, CTA 128x256, 8 warps (2x4), warp tile 64x64, 3-stage cp.async
// pipeline (stages of K=64), ldmatrix from SW128 SMEM.
// Epilogue: per 8-col group: g_tmin[row][grp] = half(-2*max(dot)).
// ---------------------------------------------------------------------------
#define GEMM_SMEM 147456   // A: 3*16KB @0, B: 3*32KB @49152

__global__ __launch_bounds__(256, 1) void select_gemm_hmma() {
    extern __shared__ char smem[];
    const uint32_t sb = smem_u32(smem);
    const int tid  = threadIdx.x;
    const int lane = tid & 31;
    const int wid  = tid >> 5;
    const int wr   = wid >> 2;       // 0..1
    const int wc   = wid & 3;        // 0..3
    const int mt   = blockIdx.y;
    const int ntile = blockIdx.x;    // 256-col N tile

    const uint4* gA = (const uint4*)g_Ap[mt];
    const uint4* gB = (const uint4*)g_Bp[ntile];

    uint32_t acc[4][8][2];
#pragma unroll
    for (int mi = 0; mi < 4; ++mi)
#pragma unroll
        for (int ni = 0; ni < 8; ++ni) { acc[mi][ni][0] = 0u; acc[mi][ni][1] = 0u; }

    auto load_chunk = [&](int kc) {
        const int st = kc % 3;
        uint32_t sA = sb + (uint32_t)st * 16384u;
        uint32_t sB = sb + 49152u + (uint32_t)st * 32768u;
        const uint4* ga = gA + kc * 1024 + tid;
        const uint4* gb = gB + kc * 2048 + tid;
#pragma unroll
        for (int i = 0; i < 4; ++i)
            CP_A16(sA + (uint32_t)(tid + i * 256) * 16u, ga + i * 256);
#pragma unroll
        for (int i = 0; i < 8; ++i)
            CP_A16(sB + (uint32_t)(tid + i * 256) * 16u, gb + i * 256);
        CP_COMMIT();
    };

    load_chunk(0);
    load_chunk(1);

    const int arow_lo = wr * 64 + (lane & 15);
    const uint32_t a_csel = (uint32_t)((lane >> 4) << 4);
    const int brow_lo = wc * 64 + ((lane >> 4) << 3) + (lane & 7);
    const uint32_t b_csel = (uint32_t)(((lane >> 3) & 1) << 4);

#pragma unroll 1
    for (int kc = 0; kc < 4; ++kc) {
        if (kc == 3) { CP_WAIT(0); } else { CP_WAIT(1); }
        __syncthreads();
        if (kc < 2) load_chunk(kc + 2);

        const int st = kc % 3;
        const uint32_t sA = sb + (uint32_t)st * 16384u;
        const uint32_t sB = sb + 49152u + (uint32_t)st * 32768u;

#pragma unroll
        for (int s = 0; s < 4; ++s) {
            uint32_t a[4][4];
#pragma unroll
            for (int mi = 0; mi < 4; ++mi) {
                int arow = arow_lo + mi * 16;
                uint32_t addr = sA + (uint32_t)arow * 128u +
                                (((uint32_t)(s * 32) + a_csel) ^ (uint32_t)((arow & 7) << 4));
                ldsm4(a[mi][0], a[mi][1], a[mi][2], a[mi][3], addr);
            }
            uint32_t b[8][2];
#pragma unroll
            for (int p = 0; p < 4; ++p) {
                int brow = brow_lo + p * 16;
                uint32_t kb = b_csel + (uint32_t)(s * 32);
                uint32_t addr = sB + (uint32_t)brow * 128u +
                                (kb ^ (uint32_t)((brow & 7) << 4));
                ldsm4(b[2 * p][0], b[2 * p][1], b[2 * p + 1][0], b[2 * p + 1][1], addr);
            }
#pragma unroll
            for (int mi = 0; mi < 4; ++mi)
#pragma unroll
                for (int ni = 0; ni < 8; ++ni) {
                    asm volatile(
                        "mma.sync.aligned.m16n8k16.row.col.f16.f16.f16.f16 "
                        "{%0,%1}, {%2,%3,%4,%5}, {%6,%7}, {%0,%1};"
                        : "+r"(acc[mi][ni][0]), "+r"(acc[mi][ni][1])
                        : "r"(a[mi][0]), "r"(a[mi][1]), "r"(a[mi][2]), "r"(a[mi][3]),
                          "r"(b[ni][0]), "r"(b[ni][1]));
                }
        }
    }

    // epilogue: per 8-col group (one ni tile): tmin = half(-2*max(dot))
    const int g   = lane >> 2;
    const int tig = lane & 3;
#pragma unroll
    for (int mi = 0; mi < 4; ++mi) {
        int r_lo = mt * 128 + wr * 64 + mi * 16 + g;
#pragma unroll
        for (int ni = 0; ni < 8; ++ni) {
            float2 lo = __half22float2(*(const __half2*)&acc[mi][ni][0]);
            float2 hi = __half22float2(*(const __half2*)&acc[mi][ni][1]);
            float m0 = fmaxf(lo.x, lo.y);
            float m1 = fmaxf(hi.x, hi.y);
            m0 = fmaxf(m0, __shfl_xor_sync(0xffffffffu, m0, 1));
            m0 = fmaxf(m0, __shfl_xor_sync(0xffffffffu, m0, 2));
            m1 = fmaxf(m1, __shfl_xor_sync(0xffffffffu, m1, 1));
            m1 = fmaxf(m1, __shfl_xor_sync(0xffffffffu, m1, 2));
            if (tig == 0) {
                int grp = ntile * 32 + wc * 8 + ni;
                g_tmin[r_lo][grp]     = __float2half_rn(-2.0f * m0);
                g_tmin[r_lo + 8][grp] = __float2half_rn(-2.0f * m1);
            }
        }
    }
}

// ---------------------------------------------------------------------------
// Exact refine + fused gather/loss (validated in R13, bit-exact argmin):
// candidates at 8-column granularity, cooperatively staged in SMEM; 8 lanes
// run the identical fp32 sequential-fmaf chain; winning row gathered
// coalesced by the same warp (output + idx + fp64 MSE).
// ---------------------------------------------------------------------------
#define REFINE_SMEM (8192 + 8 * 8320 + 64)

__global__ __launch_bounds__(256) void refine_gather_kernel(
    const float* __restrict__ x, const float* __restrict__ cb,
    float* __restrict__ outq, float* __restrict__ out_idxf,
    int write_out) {
    extern __shared__ char rsm[];
    const int tid = threadIdx.x, lane = tid & 31, wid = tid >> 5;
    const int row = blockIdx.x * 8 + wid;
    float* xs = (float*)rsm + wid * 256;
    float* es = (float*)(rsm + 8192 + wid * 8320);
    double* wsum = (double*)(rsm + 8192 + 8 * 8320);

#pragma unroll
    for (int i = 0; i < 8; ++i)
        xs[lane + 32 * i] = x[(size_t)row * 256 + lane + 32 * i];
    const float s1r = g_s1[row];
    __syncwarp();

    float tm[32];
    float gmin = __int_as_float(0x7f800000);
#pragma unroll
    for (int i = 0; i < 32; ++i) {
        tm[i] = s1r + __half2float(g_tmin[row][lane + 32 * i]);
        gmin = fminf(gmin, tm[i]);
    }
#pragma unroll
    for (int o = 16; o > 0; o >>= 1)
        gmin = fminf(gmin, __shfl_xor_sync(0xffffffffu, gmin, o));

    const float thr = gmin + 2.5e-4f;
    unsigned long long best = ~0ULL;

#pragma unroll 1
    for (int i = 0; i < 32; ++i) {
        unsigned msk = __ballot_sync(0xffffffffu, tm[i] <= thr);
        while (msk) {
            int l = __ffs(msk) - 1;
            msk &= msk - 1;
            int grp = l + 32 * i;
            int jbase = grp * 8;
            const float4* src = (const float4*)(cb + (size_t)jbase * 256);
#pragma unroll
            for (int it = 0; it < 16; ++it) {
                int idx = it * 32 + lane;
                int r = idx >> 6, c4 = idx & 63;
                float4 v = __ldg(src + r * 64 + c4);
                *(float4*)&es[r * 260 + c4 * 4] = v;
            }
            __syncwarp();
            if (lane < 8) {
                const float* e = es + lane * 260;
                float acc = 0.f;
#pragma unroll 8
                for (int k = 0; k < 256; ++k)
                    acc = __fmaf_rn(xs[k], e[k], acc);
                float d = __fsub_rn(s1r, __fmul_rn(2.0f, acc));
                int j = jbase + lane;
                unsigned long long p =
                    ((unsigned long long)__float_as_uint(d) << 32) | (unsigned)j;
                best = min(best, p);
            }
            __syncwarp();
        }
    }
#pragma unroll
    for (int o = 16; o > 0; o >>= 1) {
        unsigned long long q = __shfl_xor_sync(0xffffffffu, best, o);
        best = min(best, q);
    }
    const int bj = (int)(best & 0xffffffffULL);   // all lanes agree

    // fused gather + fp64 MSE
    double s = 0.0;
    {
        const float4* e = (const float4*)(cb + (size_t)bj * 256);
#pragma unroll
        for (int i = 0; i < 2; ++i) {
            int c = lane + i * 32;
            float4 q = __ldg(e + c);
            float vx = xs[c * 4], vy = xs[c * 4 + 1],
                  vz = xs[c * 4 + 2], vw = xs[c * 4 + 3];
            if (write_out) *((float4*)(outq + (size_t)row * 256) + c) = q;
            float d0 = __fsub_rn(q.x, vx), d1 = __fsub_rn(q.y, vy);
            float d2 = __fsub_rn(q.z, vz), d3 = __fsub_rn(q.w, vw);
            s += (double)d0 * d0 + (double)d1 * d1 + (double)d2 * d2 + (double)d3 * d3;
        }
    }
#pragma unroll
    for (int o = 16; o > 0; o >>= 1)
        s += __shfl_xor_sync(0xffffffffu, s, o);
    if (lane == 0) {
        if (write_out && out_idxf) out_idxf[row] = (float)bj;
        wsum[wid] = s;
    }
    __syncthreads();
    if (tid == 0) {
        double t = 0.0;
#pragma unroll
        for (int w = 0; w < 8; ++w) t += wsum[w];
        atomicAdd(&g_sumsq, t);
    }
}

__global__ void finalize_kernel(float* __restrict__ out_loss) {
    double m = g_sumsq / (double)(BT_N * D_N);
    float mf = (float)m;
    out_loss[0] = __fadd_rn(mf, __fmul_rn(0.25f, mf));
}

extern "C" void kernel_launch(void* const* d_in, const int* in_sizes, int n_in,
                              void* d_out, int out_size) {
    const float* x  = (const float*)d_in[0];
    const float* cb = (const float*)d_in[1];
    float* out = (float*)d_out;
    const int full = (out_size >= OUT_LOSS + 1);
    const int wq   = (out_size >= BT_N * D_N);

    cudaFuncSetAttribute(select_gemm_hmma,
                         cudaFuncAttributeMaxDynamicSharedMemorySize, GEMM_SMEM);
    cudaFuncSetAttribute(refine_gather_kernel,
                         cudaFuncAttributeMaxDynamicSharedMemorySize, REFINE_SMEM);

    init_kernel<<<1, 1>>>();
    rownorm_kernel<<<BT_N / 256, 256>>>(x);
    pack_x_kernel<<<(BT_N * 32) / 256, 256>>>(x);
    pack_e_kernel<<<(K_N * 32) / 256, 256>>>(cb);

    dim3 ggrid(K_N / 256, BT_N / 128);
    select_gemm_hmma<<<ggrid, 256, GEMM_SMEM>>>();

    refine_gather_kernel<<<BT_N / 8, 256, REFINE_SMEM>>>(
        x, cb,
        wq ? (out + OUT_Q) : (float*)0,
        full ? (out + OUT_IDX) : (float*)0,
        wq ? 1 : 0);
    if (full) {
        finalize_kernel<<<1, 1>>>(out + OUT_LOSS);
    }
}

// round 15
// speedup vs baseline: 2.0055x; 1.0715x over previous
#include <cuda_runtime.h>
#include <cuda_fp16.h>
#include <cstdint>

#define BT_N 32768
#define D_N  256
#define K_N  8192

#define OUT_Q    0
#define OUT_IDX  (BT_N * D_N)
#define OUT_LOSS (BT_N * D_N + BT_N)

// ---------------- scratch ---------------------------------------------------
__device__ float  g_s1[BT_N];
__device__ int    g_idx[BT_N];
__device__ double g_sumsq;
// Pre-swizzled fp16 operands (SW128 rows of 128B):
__device__ unsigned short g_Ap[256][4][8192];    // [m-tile][k-chunk64][128x64 sw]
__device__ unsigned short g_Bp[32][4][16384];    // [n-tile][k-chunk64][256x64 sw]
// Per-row min of approx distance over 8-column groups (1024 groups/row), fp32.
__device__ float  g_tmin[BT_N][1024];

// ---------------- helpers ---------------------------------------------------
__device__ __forceinline__ uint32_t smem_u32(const void* p) {
    uint32_t a;
    asm("{ .reg .u64 t; cvta.to.shared.u64 t, %1; cvt.u32.u64 %0, t; }"
        : "=r"(a) : "l"(p));
    return a;
}
#define SWZ128(o) ((o) ^ (((o) >> 3) & 0x70))

#define CP_A16(s, g) asm volatile("cp.async.cg.shared.global [%0], [%1], 16;\n" :: "r"(s), "l"(g))
#define CP_COMMIT()  asm volatile("cp.async.commit_group;\n" ::: "memory")
#define CP_WAIT(n)   asm volatile("cp.async.wait_group %0;\n" :: "n"(n) : "memory")

__device__ __forceinline__ void ldsm4(uint32_t& r0, uint32_t& r1, uint32_t& r2,
                                      uint32_t& r3, uint32_t addr) {
    asm volatile("ldmatrix.sync.aligned.m8n8.x4.shared.b16 {%0,%1,%2,%3}, [%4];"
                 : "=r"(r0), "=r"(r1), "=r"(r2), "=r"(r3) : "r"(addr));
}

// ---------------------------------------------------------------------------
// Row squared-norm — IDENTICAL order to round-1 (bit-exact s1 required).
// Also zeroes g_sumsq (init fused: one launch saved).
// ---------------------------------------------------------------------------
__global__ void rownorm_kernel(const float* __restrict__ x) {
    if (blockIdx.x == 0 && threadIdx.x == 0) g_sumsq = 0.0;
    int row = blockIdx.x * blockDim.x + threadIdx.x;
    if (row >= BT_N) return;
    const float4* p = reinterpret_cast<const float4*>(x + (size_t)row * D_N);
    float a0 = 0.f, a1 = 0.f, a2 = 0.f, a3 = 0.f;
#pragma unroll 8
    for (int c = 0; c < D_N / 4; ++c) {
        float4 v = __ldg(p + c);
        a0 = __fadd_rn(a0, __fmul_rn(v.x, v.x));
        a1 = __fadd_rn(a1, __fmul_rn(v.y, v.y));
        a2 = __fadd_rn(a2, __fmul_rn(v.z, v.z));
        a3 = __fadd_rn(a3, __fmul_rn(v.w, v.w));
    }
    g_s1[row] = __fadd_rn(__fadd_rn(a0, a2), __fadd_rn(a1, a3));
}

// ---------------------------------------------------------------------------
// Pack fp16 into swizzled blocked layout; thread = 8 elems (16B unit).
// ---------------------------------------------------------------------------
union U16x8 { unsigned short h[8]; uint4 u; };

__device__ __forceinline__ void cvt8(const float* src, U16x8& out) {
    float4 v0 = __ldg((const float4*)src);
    float4 v1 = __ldg((const float4*)src + 1);
    float vv[8] = {v0.x, v0.y, v0.z, v0.w, v1.x, v1.y, v1.z, v1.w};
#pragma unroll
    for (int i = 0; i < 8; ++i) {
        __half h = __float2half_rn(vv[i]);
        out.h[i] = *reinterpret_cast<unsigned short*>(&h);
    }
}

__global__ void pack_x_kernel(const float* __restrict__ x) {
    int n = blockIdx.x * blockDim.x + threadIdx.x;
    if (n >= BT_N * 32) return;
    int row = n >> 5, g = n & 31;
    int kc = g >> 3, ci = (g & 7) * 8;
    U16x8 v;
    cvt8(x + (size_t)row * 256 + g * 8, v);
    int rr = row & 127, mt = row >> 7;
    uint32_t off = SWZ128(rr * 128 + ci * 2);
    *(uint4*)((char*)g_Ap[mt][kc] + off) = v.u;
}

__global__ void pack_e_kernel(const float* __restrict__ cb) {
    int n = blockIdx.x * blockDim.x + threadIdx.x;
    if (n >= K_N * 32) return;
    int row = n >> 5, g = n & 31;
    int kc = g >> 3, ci = (g & 7) * 8;
    U16x8 v;
    cvt8(cb + (size_t)row * 256 + g * 8, v);
    int rr = row & 255, nt = row >> 8;
    uint32_t off = SWZ128(rr * 128 + ci * 2);
    *(uint4*)((char*)g_Bp[nt][kc] + off) = v.u;
}

// ---------------------------------------------------------------------------
// Selection GEMM — R6 verbatim (the empirical winner): fp16 mma.sync / fp16
// acc, K=256, CTA 128x256, 8 warps (2x4), warp tile 64x64, 3-stage cp.async
// pipeline; epilogue writes fp32 tmin per 8-col group.
// ---------------------------------------------------------------------------
#define GEMM_SMEM 147456   // A: 3*16KB @0, B: 3*32KB @49152

__global__ __launch_bounds__(256, 1) void select_gemm_hmma() {
    extern __shared__ char smem[];
    const uint32_t sb = smem_u32(smem);
    const int tid  = threadIdx.x;
    const int lane = tid & 31;
    const int wid  = tid >> 5;
    const int wr   = wid >> 2;       // 0..1
    const int wc   = wid & 3;        // 0..3
    const int mt   = blockIdx.y;
    const int ntile = blockIdx.x;    // 256-col N tile

    const uint4* gA = (const uint4*)g_Ap[mt];
    const uint4* gB = (const uint4*)g_Bp[ntile];

    uint32_t acc[4][8][2];
#pragma unroll
    for (int mi = 0; mi < 4; ++mi)
#pragma unroll
        for (int ni = 0; ni < 8; ++ni) { acc[mi][ni][0] = 0u; acc[mi][ni][1] = 0u; }

    auto load_chunk = [&](int kc) {
        const int st = kc % 3;
        uint32_t sA = sb + (uint32_t)st * 16384u;
        uint32_t sB = sb + 49152u + (uint32_t)st * 32768u;
        const uint4* ga = gA + kc * 1024 + tid;
        const uint4* gb = gB + kc * 2048 + tid;
#pragma unroll
        for (int i = 0; i < 4; ++i)
            CP_A16(sA + (uint32_t)(tid + i * 256) * 16u, ga + i * 256);
#pragma unroll
        for (int i = 0; i < 8; ++i)
            CP_A16(sB + (uint32_t)(tid + i * 256) * 16u, gb + i * 256);
        CP_COMMIT();
    };

    load_chunk(0);
    load_chunk(1);

    const int arow_lo = wr * 64 + (lane & 15);
    const uint32_t a_csel = (uint32_t)((lane >> 4) << 4);
    const int brow_lo = wc * 64 + ((lane >> 4) << 3) + (lane & 7);
    const uint32_t b_csel = (uint32_t)(((lane >> 3) & 1) << 4);

#pragma unroll 1
    for (int kc = 0; kc < 4; ++kc) {
        if (kc == 3) { CP_WAIT(0); } else { CP_WAIT(1); }
        __syncthreads();
        if (kc < 2) load_chunk(kc + 2);

        const int st = kc % 3;
        const uint32_t sA = sb + (uint32_t)st * 16384u;
        const uint32_t sB = sb + 49152u + (uint32_t)st * 32768u;

#pragma unroll
        for (int s = 0; s < 4; ++s) {
            uint32_t a[4][4];
#pragma unroll
            for (int mi = 0; mi < 4; ++mi) {
                int arow = arow_lo + mi * 16;
                uint32_t addr = sA + (uint32_t)arow * 128u +
                                (((uint32_t)(s * 32) + a_csel) ^ (uint32_t)((arow & 7) << 4));
                ldsm4(a[mi][0], a[mi][1], a[mi][2], a[mi][3], addr);
            }
            uint32_t b[8][2];
#pragma unroll
            for (int p = 0; p < 4; ++p) {
                int brow = brow_lo + p * 16;
                uint32_t kb = b_csel + (uint32_t)(s * 32);
                uint32_t addr = sB + (uint32_t)brow * 128u +
                                (kb ^ (uint32_t)((brow & 7) << 4));
                ldsm4(b[2 * p][0], b[2 * p][1], b[2 * p + 1][0], b[2 * p + 1][1], addr);
            }
#pragma unroll
            for (int mi = 0; mi < 4; ++mi)
#pragma unroll
                for (int ni = 0; ni < 8; ++ni) {
                    asm volatile(
                        "mma.sync.aligned.m16n8k16.row.col.f16.f16.f16.f16 "
                        "{%0,%1}, {%2,%3,%4,%5}, {%6,%7}, {%0,%1};"
                        : "+r"(acc[mi][ni][0]), "+r"(acc[mi][ni][1])
                        : "r"(a[mi][0]), "r"(a[mi][1]), "r"(a[mi][2]), "r"(a[mi][3]),
                          "r"(b[ni][0]), "r"(b[ni][1]));
                }
        }
    }

    // epilogue: per 8-col group (one ni tile) min of d~ = s1 - 2*max(dot)
    const int g   = lane >> 2;
    const int tig = lane & 3;
#pragma unroll
    for (int mi = 0; mi < 4; ++mi) {
        int r_lo = mt * 128 + wr * 64 + mi * 16 + g;
        float s1a = g_s1[r_lo], s1b = g_s1[r_lo + 8];
#pragma unroll
        for (int ni = 0; ni < 8; ++ni) {
            float2 lo = __half22float2(*(const __half2*)&acc[mi][ni][0]);
            float2 hi = __half22float2(*(const __half2*)&acc[mi][ni][1]);
            float m0 = fmaxf(lo.x, lo.y);
            float m1 = fmaxf(hi.x, hi.y);
            m0 = fmaxf(m0, __shfl_xor_sync(0xffffffffu, m0, 1));
            m0 = fmaxf(m0, __shfl_xor_sync(0xffffffffu, m0, 2));
            m1 = fmaxf(m1, __shfl_xor_sync(0xffffffffu, m1, 1));
            m1 = fmaxf(m1, __shfl_xor_sync(0xffffffffu, m1, 2));
            if (tig == 0) {
                int grp = ntile * 32 + wc * 8 + ni;
                g_tmin[r_lo][grp]     = s1a - 2.0f * m0;
                g_tmin[r_lo + 8][grp] = s1b - 2.0f * m1;
            }
        }
    }
}

// ---------------------------------------------------------------------------
// Exact refine — R6 verbatim (fp32 tmin, margin 2.0e-4, bit-exact argmin).
// ---------------------------------------------------------------------------
#define REFINE_SMEM (8192 + 8 * 8320)

__global__ __launch_bounds__(256) void refine_kernel(
    const float* __restrict__ x, const float* __restrict__ cb,
    float* __restrict__ out_idxf, int write_idxf) {
    extern __shared__ char rsm[];
    const int tid = threadIdx.x, lane = tid & 31, wid = tid >> 5;
    const int row = blockIdx.x * 8 + wid;
    float* xs = (float*)rsm + wid * 256;
    float* es = (float*)(rsm + 8192 + wid * 8320);

#pragma unroll
    for (int i = 0; i < 8; ++i)
        xs[lane + 32 * i] = x[(size_t)row * 256 + lane + 32 * i];
    const float s1r = g_s1[row];
    __syncwarp();

    float tm[32];
    float gmin = __int_as_float(0x7f800000);
#pragma unroll
    for (int i = 0; i < 32; ++i) {
        tm[i] = g_tmin[row][lane + 32 * i];
        gmin = fminf(gmin, tm[i]);
    }
#pragma unroll
    for (int o = 16; o > 0; o >>= 1)
        gmin = fminf(gmin, __shfl_xor_sync(0xffffffffu, gmin, o));

    const float thr = gmin + 2.0e-4f;
    unsigned long long best = ~0ULL;

#pragma unroll 1
    for (int i = 0; i < 32; ++i) {
        unsigned msk = __ballot_sync(0xffffffffu, tm[i] <= thr);
        while (msk) {
            int l = __ffs(msk) - 1;
            msk &= msk - 1;
            int grp = l + 32 * i;
            int jbase = grp * 8;
            const float4* src = (const float4*)(cb + (size_t)jbase * 256);
#pragma unroll
            for (int it = 0; it < 16; ++it) {
                int idx = it * 32 + lane;
                int r = idx >> 6, c4 = idx & 63;
                float4 v = __ldg(src + r * 64 + c4);
                *(float4*)&es[r * 260 + c4 * 4] = v;
            }
            __syncwarp();
            if (lane < 8) {
                const float* e = es + lane * 260;
                float acc = 0.f;
#pragma unroll 8
                for (int k = 0; k < 256; ++k)
                    acc = __fmaf_rn(xs[k], e[k], acc);
                float d = __fsub_rn(s1r, __fmul_rn(2.0f, acc));
                int j = jbase + lane;
                unsigned long long p =
                    ((unsigned long long)__float_as_uint(d) << 32) | (unsigned)j;
                best = min(best, p);
            }
            __syncwarp();
        }
    }
#pragma unroll
    for (int o = 16; o > 0; o >>= 1) {
        unsigned long long q = __shfl_xor_sync(0xffffffffu, best, o);
        best = min(best, q);
    }
    if (lane == 0) {
        int bj = (int)(best & 0xffffffffULL);
        g_idx[row] = bj;
        if (write_idxf) out_idxf[row] = (float)bj;
    }
}

// ---------------------------------------------------------------------------
// Gather v2: warp per row, float4-coalesced, one idx load per row; fp64 MSE.
// ---------------------------------------------------------------------------
__global__ __launch_bounds__(256) void gather_mse_kernel(
    const float* __restrict__ x, const float* __restrict__ cb,
    float* __restrict__ outq) {
    __shared__ double red[256];
    const int lane = threadIdx.x & 31, wid = threadIdx.x >> 5;
    const int row = blockIdx.x * 8 + wid;
    const int idx = g_idx[row];
    const float4* e = (const float4*)(cb + (size_t)idx * 256);
    const float4* xr = (const float4*)(x + (size_t)row * 256);
    float4* o = (float4*)(outq + (size_t)row * 256);
    double s = 0.0;
#pragma unroll
    for (int i = 0; i < 2; ++i) {
        int c = lane + i * 32;
        float4 q = __ldg(e + c);
        float4 v = __ldg(xr + c);
        o[c] = q;
        float d0 = __fsub_rn(q.x, v.x), d1 = __fsub_rn(q.y, v.y);
        float d2 = __fsub_rn(q.z, v.z), d3 = __fsub_rn(q.w, v.w);
        s += (double)d0 * d0 + (double)d1 * d1 + (double)d2 * d2 + (double)d3 * d3;
    }
    red[threadIdx.x] = s;
    __syncthreads();
    for (int o2 = 128; o2 > 0; o2 >>= 1) {
        if (threadIdx.x < o2) red[threadIdx.x] += red[threadIdx.x + o2];
        __syncthreads();
    }
    if (threadIdx.x == 0) atomicAdd(&g_sumsq, red[0]);
}

__global__ void finalize_kernel(float* __restrict__ out_loss) {
    double m = g_sumsq / (double)(BT_N * D_N);
    float mf = (float)m;
    out_loss[0] = __fadd_rn(mf, __fmul_rn(0.25f, mf));
}

extern "C" void kernel_launch(void* const* d_in, const int* in_sizes, int n_in,
                              void* d_out, int out_size) {
    const float* x  = (const float*)d_in[0];
    const float* cb = (const float*)d_in[1];
    float* out = (float*)d_out;
    const int full = (out_size >= OUT_LOSS + 1);
    const int wq   = (out_size >= BT_N * D_N);

    cudaFuncSetAttribute(select_gemm_hmma,
                         cudaFuncAttributeMaxDynamicSharedMemorySize, GEMM_SMEM);
    cudaFuncSetAttribute(refine_kernel,
                         cudaFuncAttributeMaxDynamicSharedMemorySize, REFINE_SMEM);

    rownorm_kernel<<<BT_N / 256, 256>>>(x);
    pack_x_kernel<<<(BT_N * 32) / 256, 256>>>(x);
    pack_e_kernel<<<(K_N * 32) / 256, 256>>>(cb);

    dim3 ggrid(K_N / 256, BT_N / 128);
    select_gemm_hmma<<<ggrid, 256, GEMM_SMEM>>>();

    refine_kernel<<<BT_N / 8, 256, REFINE_SMEM>>>(x, cb,
                                                  full ? (out + OUT_IDX) : (float*)0,
                                                  full ? 1 : 0);
    if (wq) {
        gather_mse_kernel<<<BT_N / 8, 256>>>(x, cb, out + OUT_Q);
    }
    if (full) {
        finalize_kernel<<<1, 1>>>(out + OUT_LOSS);
    }
}

// round 17
// speedup vs baseline: 2.4697x; 1.2315x over previous
#include <cuda_runtime.h>
#include <cuda_fp16.h>
#include <cstdint>

#define BT_N 32768
#define D_N  256
#define K_N  8192

#define OUT_Q    0
#define OUT_IDX  (BT_N * D_N)
#define OUT_LOSS (BT_N * D_N + BT_N)

// ---------------- scratch ---------------------------------------------------
__device__ float  g_s1[BT_N];
__device__ int    g_idx[BT_N];
__device__ double g_sumsq;
// Pre-swizzled fp16 operands (SW128 rows of 128B):
__device__ unsigned short g_Ap[256][4][8192];    // [m-tile128][k-chunk64][128x64 sw]
__device__ unsigned short g_Bp[64][4][8192];     // [n-tile128][k-chunk64][128x64 sw]
// Per-row min of approx distance over 8-column groups (1024 groups/row), fp32.
__device__ float  g_tmin[BT_N][1024];

// ---------------- helpers ---------------------------------------------------
__device__ __forceinline__ uint32_t smem_u32(const void* p) {
    uint32_t a;
    asm("{ .reg .u64 t; cvta.to.shared.u64 t, %1; cvt.u32.u64 %0, t; }"
        : "=r"(a) : "l"(p));
    return a;
}
#define SWZ128(o) ((o) ^ (((o) >> 3) & 0x70))

#define CP_A16(s, g) asm volatile("cp.async.cg.shared.global [%0], [%1], 16;\n" :: "r"(s), "l"(g))
#define CP_COMMIT()  asm volatile("cp.async.commit_group;\n" ::: "memory")
#define CP_WAIT(n)   asm volatile("cp.async.wait_group %0;\n" :: "n"(n) : "memory")

__device__ __forceinline__ void ldsm4(uint32_t& r0, uint32_t& r1, uint32_t& r2,
                                      uint32_t& r3, uint32_t addr) {
    asm volatile("ldmatrix.sync.aligned.m8n8.x4.shared.b16 {%0,%1,%2,%3}, [%4];"
                 : "=r"(r0), "=r"(r1), "=r"(r2), "=r"(r3) : "r"(addr));
}

// ---------------------------------------------------------------------------
// Row squared-norm — IDENTICAL order to round-1 (bit-exact s1 required).
// Also zeroes g_sumsq.
// ---------------------------------------------------------------------------
__global__ void rownorm_kernel(const float* __restrict__ x) {
    if (blockIdx.x == 0 && threadIdx.x == 0) g_sumsq = 0.0;
    int row = blockIdx.x * blockDim.x + threadIdx.x;
    if (row >= BT_N) return;
    const float4* p = reinterpret_cast<const float4*>(x + (size_t)row * D_N);
    float a0 = 0.f, a1 = 0.f, a2 = 0.f, a3 = 0.f;
#pragma unroll 8
    for (int c = 0; c < D_N / 4; ++c) {
        float4 v = __ldg(p + c);
        a0 = __fadd_rn(a0, __fmul_rn(v.x, v.x));
        a1 = __fadd_rn(a1, __fmul_rn(v.y, v.y));
        a2 = __fadd_rn(a2, __fmul_rn(v.z, v.z));
        a3 = __fadd_rn(a3, __fmul_rn(v.w, v.w));
    }
    g_s1[row] = __fadd_rn(__fadd_rn(a0, a2), __fadd_rn(a1, a3));
}

// ---------------------------------------------------------------------------
// Pack fp16 into swizzled blocked layout; thread = 8 elems (16B unit).
// ---------------------------------------------------------------------------
union U16x8 { unsigned short h[8]; uint4 u; };

__device__ __forceinline__ void cvt8(const float* src, U16x8& out) {
    float4 v0 = __ldg((const float4*)src);
    float4 v1 = __ldg((const float4*)src + 1);
    float vv[8] = {v0.x, v0.y, v0.z, v0.w, v1.x, v1.y, v1.z, v1.w};
#pragma unroll
    for (int i = 0; i < 8; ++i) {
        __half h = __float2half_rn(vv[i]);
        out.h[i] = *reinterpret_cast<unsigned short*>(&h);
    }
}

__global__ void pack_x_kernel(const float* __restrict__ x) {
    int n = blockIdx.x * blockDim.x + threadIdx.x;
    if (n >= BT_N * 32) return;
    int row = n >> 5, g = n & 31;
    int kc = g >> 3, ci = (g & 7) * 8;
    U16x8 v;
    cvt8(x + (size_t)row * 256 + g * 8, v);
    int rr = row & 127, mt = row >> 7;
    uint32_t off = SWZ128(rr * 128 + ci * 2);
    *(uint4*)((char*)g_Ap[mt][kc] + off) = v.u;
}

__global__ void pack_e_kernel(const float* __restrict__ cb) {
    int n = blockIdx.x * blockDim.x + threadIdx.x;
    if (n >= K_N * 32) return;
    int row = n >> 5, g = n & 31;
    int kc = g >> 3, ci = (g & 7) * 8;
    U16x8 v;
    cvt8(cb + (size_t)row * 256 + g * 8, v);
    int rr = row & 127, nt = row >> 7;    // 128-row n-tiles now
    uint32_t off = SWZ128(rr * 128 + ci * 2);
    *(uint4*)((char*)g_Bp[nt][kc] + off) = v.u;
}

// ---------------------------------------------------------------------------
// Selection GEMM v2: same 64x64 warp tile / fp16-acc mainloop as R6, but
// CTA = 128x128 with 4 warps (128 threads), 2-stage 64KB pipeline ->
// 3 CTAs/SM = 12 warps (occupancy fix for the measured 46.6% tensor util).
// Epilogue: per 8-col group: g_tmin[row][grp] = s1 - 2*max(dot).
// ---------------------------------------------------------------------------
#define GEMM_SMEM 65536   // A: 2*16KB @0, B: 2*16KB @32768

__global__ __launch_bounds__(128, 3) void select_gemm_hmma() {
    extern __shared__ char smem[];
    const uint32_t sb = smem_u32(smem);
    const int tid  = threadIdx.x;
    const int lane = tid & 31;
    const int wid  = tid >> 5;
    const int wr   = wid >> 1;       // 0..1
    const int wc   = wid & 1;        // 0..1
    const int mt   = blockIdx.y;
    const int ntile = blockIdx.x;    // 128-col N tile

    const uint4* gA = (const uint4*)g_Ap[mt];
    const uint4* gB = (const uint4*)g_Bp[ntile];

    uint32_t acc[4][8][2];
#pragma unroll
    for (int mi = 0; mi < 4; ++mi)
#pragma unroll
        for (int ni = 0; ni < 8; ++ni) { acc[mi][ni][0] = 0u; acc[mi][ni][1] = 0u; }

    auto load_chunk = [&](int kc) {
        const int st = kc & 1;
        uint32_t sA = sb + (uint32_t)st * 16384u;
        uint32_t sB = sb + 32768u + (uint32_t)st * 16384u;
        const uint4* ga = gA + kc * 1024 + tid;
        const uint4* gb = gB + kc * 1024 + tid;
#pragma unroll
        for (int i = 0; i < 8; ++i)
            CP_A16(sA + (uint32_t)(tid + i * 128) * 16u, ga + i * 128);
#pragma unroll
        for (int i = 0; i < 8; ++i)
            CP_A16(sB + (uint32_t)(tid + i * 128) * 16u, gb + i * 128);
        CP_COMMIT();
    };

    load_chunk(0);

    const int arow_lo = wr * 64 + (lane & 15);
    const uint32_t a_csel = (uint32_t)((lane >> 4) << 4);
    const int brow_lo = wc * 64 + ((lane >> 4) << 3) + (lane & 7);
    const uint32_t b_csel = (uint32_t)(((lane >> 3) & 1) << 4);

#pragma unroll 1
    for (int kc = 0; kc < 4; ++kc) {
        if (kc < 3) load_chunk(kc + 1);
        if (kc < 3) { CP_WAIT(1); } else { CP_WAIT(0); }
        __syncthreads();

        const int st = kc & 1;
        const uint32_t sA = sb + (uint32_t)st * 16384u;
        const uint32_t sB = sb + 32768u + (uint32_t)st * 16384u;

#pragma unroll
        for (int s = 0; s < 4; ++s) {
            uint32_t a[4][4];
#pragma unroll
            for (int mi = 0; mi < 4; ++mi) {
                int arow = arow_lo + mi * 16;
                uint32_t addr = sA + (uint32_t)arow * 128u +
                                (((uint32_t)(s * 32) + a_csel) ^ (uint32_t)((arow & 7) << 4));
                ldsm4(a[mi][0], a[mi][1], a[mi][2], a[mi][3], addr);
            }
            uint32_t b[8][2];
#pragma unroll
            for (int p = 0; p < 4; ++p) {
                int brow = brow_lo + p * 16;
                uint32_t kb = b_csel + (uint32_t)(s * 32);
                uint32_t addr = sB + (uint32_t)brow * 128u +
                                (kb ^ (uint32_t)((brow & 7) << 4));
                ldsm4(b[2 * p][0], b[2 * p][1], b[2 * p + 1][0], b[2 * p + 1][1], addr);
            }
#pragma unroll
            for (int mi = 0; mi < 4; ++mi)
#pragma unroll
                for (int ni = 0; ni < 8; ++ni) {
                    asm volatile(
                        "mma.sync.aligned.m16n8k16.row.col.f16.f16.f16.f16 "
                        "{%0,%1}, {%2,%3,%4,%5}, {%6,%7}, {%0,%1};"
                        : "+r"(acc[mi][ni][0]), "+r"(acc[mi][ni][1])
                        : "r"(a[mi][0]), "r"(a[mi][1]), "r"(a[mi][2]), "r"(a[mi][3]),
                          "r"(b[ni][0]), "r"(b[ni][1]));
                }
        }
        __syncthreads();   // all warps done with stage before it is overwritten
    }

    // epilogue: per 8-col group (one ni tile) min of d~ = s1 - 2*max(dot)
    const int g   = lane >> 2;
    const int tig = lane & 3;
#pragma unroll
    for (int mi = 0; mi < 4; ++mi) {
        int r_lo = mt * 128 + wr * 64 + mi * 16 + g;
        float s1a = g_s1[r_lo], s1b = g_s1[r_lo + 8];
#pragma unroll
        for (int ni = 0; ni < 8; ++ni) {
            float2 lo = __half22float2(*(const __half2*)&acc[mi][ni][0]);
            float2 hi = __half22float2(*(const __half2*)&acc[mi][ni][1]);
            float m0 = fmaxf(lo.x, lo.y);
            float m1 = fmaxf(hi.x, hi.y);
            m0 = fmaxf(m0, __shfl_xor_sync(0xffffffffu, m0, 1));
            m0 = fmaxf(m0, __shfl_xor_sync(0xffffffffu, m0, 2));
            m1 = fmaxf(m1, __shfl_xor_sync(0xffffffffu, m1, 1));
            m1 = fmaxf(m1, __shfl_xor_sync(0xffffffffu, m1, 2));
            if (tig == 0) {
                int grp = ntile * 16 + wc * 8 + ni;
                g_tmin[r_lo][grp]     = s1a - 2.0f * m0;
                g_tmin[r_lo + 8][grp] = s1b - 2.0f * m1;
            }
        }
    }
}

// ---------------------------------------------------------------------------
// Exact refine — R6 verbatim (fp32 tmin, margin 2.0e-4, bit-exact argmin).
// ---------------------------------------------------------------------------
#define REFINE_SMEM (8192 + 8 * 8320)

__global__ __launch_bounds__(256) void refine_kernel(
    const float* __restrict__ x, const float* __restrict__ cb,
    float* __restrict__ out_idxf, int write_idxf) {
    extern __shared__ char rsm[];
    const int tid = threadIdx.x, lane = tid & 31, wid = tid >> 5;
    const int row = blockIdx.x * 8 + wid;
    float* xs = (float*)rsm + wid * 256;
    float* es = (float*)(rsm + 8192 + wid * 8320);

#pragma unroll
    for (int i = 0; i < 8; ++i)
        xs[lane + 32 * i] = x[(size_t)row * 256 + lane + 32 * i];
    const float s1r = g_s1[row];
    __syncwarp();

    float tm[32];
    float gmin = __int_as_float(0x7f800000);
#pragma unroll
    for (int i = 0; i < 32; ++i) {
        tm[i] = g_tmin[row][lane + 32 * i];
        gmin = fminf(gmin, tm[i]);
    }
#pragma unroll
    for (int o = 16; o > 0; o >>= 1)
        gmin = fminf(gmin, __shfl_xor_sync(0xffffffffu, gmin, o));

    const float thr = gmin + 2.0e-4f;
    unsigned long long best = ~0ULL;

#pragma unroll 1
    for (int i = 0; i < 32; ++i) {
        unsigned msk = __ballot_sync(0xffffffffu, tm[i] <= thr);
        while (msk) {
            int l = __ffs(msk) - 1;
            msk &= msk - 1;
            int grp = l + 32 * i;
            int jbase = grp * 8;
            const float4* src = (const float4*)(cb + (size_t)jbase * 256);
#pragma unroll
            for (int it = 0; it < 16; ++it) {
                int idx = it * 32 + lane;
                int r = idx >> 6, c4 = idx & 63;
                float4 v = __ldg(src + r * 64 + c4);
                *(float4*)&es[r * 260 + c4 * 4] = v;
            }
            __syncwarp();
            if (lane < 8) {
                const float* e = es + lane * 260;
                float acc = 0.f;
#pragma unroll 8
                for (int k = 0; k < 256; ++k)
                    acc = __fmaf_rn(xs[k], e[k], acc);
                float d = __fsub_rn(s1r, __fmul_rn(2.0f, acc));
                int j = jbase + lane;
                unsigned long long p =
                    ((unsigned long long)__float_as_uint(d) << 32) | (unsigned)j;
                best = min(best, p);
            }
            __syncwarp();
        }
    }
#pragma unroll
    for (int o = 16; o > 0; o >>= 1) {
        unsigned long long q = __shfl_xor_sync(0xffffffffu, best, o);
        best = min(best, q);
    }
    if (lane == 0) {
        int bj = (int)(best & 0xffffffffULL);
        g_idx[row] = bj;
        if (write_idxf) out_idxf[row] = (float)bj;
    }
}

// ---------------------------------------------------------------------------
// Gather v2: warp per row, float4-coalesced, one idx load per row; fp64 MSE.
// ---------------------------------------------------------------------------
__global__ __launch_bounds__(256) void gather_mse_kernel(
    const float* __restrict__ x, const float* __restrict__ cb,
    float* __restrict__ outq) {
    __shared__ double red[256];
    const int lane = threadIdx.x & 31, wid = threadIdx.x >> 5;
    const int row = blockIdx.x * 8 + wid;
    const int idx = g_idx[row];
    const float4* e = (const float4*)(cb + (size_t)idx * 256);
    const float4* xr = (const float4*)(x + (size_t)row * 256);
    float4* o = (float4*)(outq + (size_t)row * 256);
    double s = 0.0;
#pragma unroll
    for (int i = 0; i < 2; ++i) {
        int c = lane + i * 32;
        float4 q = __ldg(e + c);
        float4 v = __ldg(xr + c);
        o[c] = q;
        float d0 = __fsub_rn(q.x, v.x), d1 = __fsub_rn(q.y, v.y);
        float d2 = __fsub_rn(q.z, v.z), d3 = __fsub_rn(q.w, v.w);
        s += (double)d0 * d0 + (double)d1 * d1 + (double)d2 * d2 + (double)d3 * d3;
    }
    red[threadIdx.x] = s;
    __syncthreads();
    for (int o2 = 128; o2 > 0; o2 >>= 1) {
        if (threadIdx.x < o2) red[threadIdx.x] += red[threadIdx.x + o2];
        __syncthreads();
    }
    if (threadIdx.x == 0) atomicAdd(&g_sumsq, red[0]);
}

__global__ void finalize_kernel(float* __restrict__ out_loss) {
    double m = g_sumsq / (double)(BT_N * D_N);
    float mf = (float)m;
    out_loss[0] = __fadd_rn(mf, __fmul_rn(0.25f, mf));
}

extern "C" void kernel_launch(void* const* d_in, const int* in_sizes, int n_in,
                              void* d_out, int out_size) {
    const float* x  = (const float*)d_in[0];
    const float* cb = (const float*)d_in[1];
    float* out = (float*)d_out;
    const int full = (out_size >= OUT_LOSS + 1);
    const int wq   = (out_size >= BT_N * D_N);

    cudaFuncSetAttribute(select_gemm_hmma,
                         cudaFuncAttributeMaxDynamicSharedMemorySize, GEMM_SMEM);
    cudaFuncSetAttribute(refine_kernel,
                         cudaFuncAttributeMaxDynamicSharedMemorySize, REFINE_SMEM);

    rownorm_kernel<<<BT_N / 256, 256>>>(x);
    pack_x_kernel<<<(BT_N * 32) / 256, 256>>>(x);
    pack_e_kernel<<<(K_N * 32) / 256, 256>>>(cb);

    dim3 ggrid(K_N / 128, BT_N / 128);   // 64 n-tiles x 256 m-tiles
    select_gemm_hmma<<<ggrid, 128, GEMM_SMEM>>>();

    refine_kernel<<<BT_N / 8, 256, REFINE_SMEM>>>(x, cb,
                                                  full ? (out + OUT_IDX) : (float*)0,
                                                  full ? 1 : 0);
    if (wq) {
        gather_mse_kernel<<<BT_N / 8, 256>>>(x, cb, out + OUT_Q);
    }
    if (full) {
        finalize_kernel<<<1, 1>>>(out + OUT_LOSS);
    }
}